// round 7
// baseline (speedup 1.0000x reference)
#include <cuda_runtime.h>
#include <math.h>
#include <stdint.h>

#define T_TOK 4096
#define D_DIM 1024
#define E_NUM 8
#define H_DIM 2816

__device__ int   g_cnt[E_NUM];
__device__ int   g_slot_tok[E_NUM * T_TOK];
__device__ float g_slot_w[E_NUM * T_TOK];
__device__ int   g_tok_slot[T_TOK * 2];
__device__ float g_h[(size_t)E_NUM * T_TOK * H_DIM];
__device__ float g_down[(size_t)E_NUM * T_TOK * D_DIM];

// ---------------- helpers ----------------
__device__ __forceinline__ uint32_t smem_u32(const void* p){
    uint32_t a; asm("{ .reg .u64 t; cvta.to.shared.u64 t, %1; cvt.u32.u64 %0, t; }" : "=r"(a) : "l"(p)); return a;
}
__device__ __forceinline__ uint32_t tfo(uint32_t bits){
    uint32_t r; asm("cvt.rna.tf32.f32 %0, %1;" : "=r"(r) : "f"(__uint_as_float(bits))); return r;
}
__device__ __forceinline__ void mma8(float* c, const uint32_t* a, const uint32_t* b){
    asm volatile("mma.sync.aligned.m16n8k8.row.col.f32.tf32.tf32.f32 "
        "{%0,%1,%2,%3}, {%4,%5,%6,%7}, {%8,%9}, {%0,%1,%2,%3};"
        : "+f"(c[0]), "+f"(c[1]), "+f"(c[2]), "+f"(c[3])
        : "r"(a[0]), "r"(a[1]), "r"(a[2]), "r"(a[3]), "r"(b[0]), "r"(b[1]));
}
__device__ __forceinline__ float silu_mul(float g, float u){
    return (g / (1.f + expf(-g))) * u;
}
__device__ __forceinline__ void cpa16(uint32_t dst, const void* src){
    asm volatile("cp.async.cg.shared.global [%0], [%1], 16;" :: "r"(dst), "l"(src) : "memory");
}
#define CP_COMMIT() asm volatile("cp.async.commit_group;" ::: "memory")
#define CP_WAIT0()  asm volatile("cp.async.wait_group 0;" ::: "memory")

// ---------------- small kernels ----------------
__global__ void zero_cnt_kernel() { if (threadIdx.x < E_NUM) g_cnt[threadIdx.x] = 0; }

__global__ __launch_bounds__(256) void gating_kernel(const float* __restrict__ x,
                                                     const float* __restrict__ wg){
    __shared__ float s_red[E_NUM][256];
    const int t = blockIdx.x, tid = threadIdx.x;
    const float* xr = x + (size_t)t * D_DIM;
    float part[E_NUM];
#pragma unroll
    for (int e = 0; e < E_NUM; e++) part[e] = 0.f;
    for (int d = tid; d < D_DIM; d += 256) {
        const float xv = xr[d];
        const float* w = wg + (size_t)d * E_NUM;
#pragma unroll
        for (int e = 0; e < E_NUM; e++) part[e] += xv * w[e];
    }
#pragma unroll
    for (int e = 0; e < E_NUM; e++) s_red[e][tid] = part[e];
    __syncthreads();
    for (int s = 128; s > 0; s >>= 1) {
        if (tid < s) {
#pragma unroll
            for (int e = 0; e < E_NUM; e++) s_red[e][tid] += s_red[e][tid + s];
        }
        __syncthreads();
    }
    if (tid == 0) {
        float p[E_NUM]; float mx = -1e30f;
#pragma unroll
        for (int e = 0; e < E_NUM; e++) mx = fmaxf(mx, s_red[e][0]);
#pragma unroll
        for (int e = 0; e < E_NUM; e++) p[e] = expf(s_red[e][0] - mx);
        int i1 = 0;
#pragma unroll
        for (int e = 1; e < E_NUM; e++) if (p[e] > p[i1]) i1 = e;
        int i2 = (i1 == 0) ? 1 : 0;
#pragma unroll
        for (int e = 0; e < E_NUM; e++) if (e != i1 && p[e] > p[i2]) i2 = e;
        const float ws = p[i1] + p[i2];
        const int s0 = atomicAdd(&g_cnt[i1], 1);
        const int s1 = atomicAdd(&g_cnt[i2], 1);
        g_slot_tok[i1 * T_TOK + s0] = t;  g_slot_w[i1 * T_TOK + s0] = p[i1] / ws;
        g_slot_tok[i2 * T_TOK + s1] = t;  g_slot_w[i2 * T_TOK + s1] = p[i2] / ws;
        g_tok_slot[2 * t + 0] = i1 * T_TOK + s0;
        g_tok_slot[2 * t + 1] = i2 * T_TOK + s1;
    }
}

__global__ __launch_bounds__(256) void combine_kernel(float* __restrict__ out){
    const int t = blockIdx.x, i = threadIdx.x;
    const int s0 = g_tok_slot[2 * t + 0], s1 = g_tok_slot[2 * t + 1];
    const float4 a = *(const float4*)(g_down + (size_t)s0 * D_DIM + i * 4);
    const float4 b = *(const float4*)(g_down + (size_t)s1 * D_DIM + i * 4);
    float4 o; o.x = a.x + b.x; o.y = a.y + b.y; o.z = a.z + b.z; o.w = a.w + b.w;
    *(float4*)(out + (size_t)t * D_DIM + i * 4) = o;
}

// Dynamic SMEM layouts (uint32 words):
// gemm13 per buffer: A[128][36] (4608) | B1[32][68] (2176) | B3[32][68] (2176) = 8960 words
// gemm2  per buffer: A[128][36] (4608) | B[32][132] (4224)                     = 8832 words
#define BUF13_W 8960
#define B1_OFF  4608
#define B3_OFF  6784
#define BUF2_W  8832
#define B2_OFF  4608

extern __shared__ uint32_t dyn[];

// ---------------- gemm13: h = silu(X@w1) * (X@w3) ----------------
// BM=128, BN=64 per matrix, BK=32. 8 warps (2M x 4N), warp tile 64x16 per matrix.
__global__ __launch_bounds__(256, 2) void gemm13_mma(const float* __restrict__ x,
                                                     const float* __restrict__ w1,
                                                     const float* __restrict__ w3){
    const int e = blockIdx.z, cnt = g_cnt[e], m0 = blockIdx.y * 128;
    if (m0 >= cnt) return;
    const int n0 = blockIdx.x * 64;

    __shared__ int s_row[128];
    const uint32_t sbase = smem_u32(dyn);

    const int tid = threadIdx.x, wid = tid >> 5, lane = tid & 31;
    const int gq = lane >> 2, tq = lane & 3;
    const int warp_m = (wid & 1) * 64, warp_n = (wid >> 1) * 16;

    if (tid < 128) s_row[tid] = g_slot_tok[e * T_TOK + min(m0 + tid, cnt - 1)];
    __syncthreads();

    // A staging: row tid>>1, k cols (tid&1)*16 + i*4 (4 cpa16)
    const int arow = tid >> 1, ak0 = (tid & 1) * 16;
    const float* xA = x + (size_t)s_row[arow] * D_DIM + ak0;
    const uint32_t dA = sbase + (uint32_t)(arow * 36 + ak0) * 4;

    // B staging: threads 0-127 -> B1, 128-255 -> B3. row (tid&127)>>2, cols (tid&3)*16 + i*4
    const int bt = tid & 127;
    const int bkk = bt >> 2, bn0 = (bt & 3) * 16;
    const float* wB = ((tid < 128) ? w1 : w3) + ((size_t)e * D_DIM + bkk) * H_DIM + n0 + bn0;
    const uint32_t dB = sbase + (uint32_t)(((tid < 128) ? B1_OFF : B3_OFF) + bkk * 68 + bn0) * 4;

    float accg[4][2][4], accu[4][2][4];
#pragma unroll
    for (int i = 0; i < 4; i++)
#pragma unroll
        for (int j = 0; j < 2; j++)
#pragma unroll
            for (int q = 0; q < 4; q++) { accg[i][j][q] = 0.f; accu[i][j][q] = 0.f; }

    const int NC = D_DIM / 32;

    // prologue: chunk 0 -> buffer 0
    {
#pragma unroll
        for (int i = 0; i < 4; i++) cpa16(dA + i * 16, xA + i * 4);
#pragma unroll
        for (int i = 0; i < 4; i++) cpa16(dB + i * 16, wB + i * 4);
        CP_COMMIT();
    }

    for (int c = 0; c < NC; c++) {
        CP_WAIT0();
        __syncthreads();

        if (c + 1 < NC) {
            const uint32_t bo = (uint32_t)(((c + 1) & 1) * BUF13_W) * 4;
            const int kg = (c + 1) * 32;
            const float* pB = wB + (size_t)kg * H_DIM;
#pragma unroll
            for (int i = 0; i < 4; i++) cpa16(dA + bo + i * 16, xA + kg + i * 4);
#pragma unroll
            for (int i = 0; i < 4; i++) cpa16(dB + bo + i * 16, pB + i * 4);
        }
        CP_COMMIT();

        const uint32_t* Ab  = dyn + (c & 1) * BUF13_W;
        const uint32_t* B1b = Ab + B1_OFF;
        const uint32_t* B3b = Ab + B3_OFF;

#pragma unroll
        for (int ks = 0; ks < 4; ks++) {
            const int k0 = ks * 8;
            uint32_t af[4][4];
#pragma unroll
            for (int i = 0; i < 4; i++) {
                const int m = warp_m + i * 16;
                af[i][0] = tfo(Ab[(m + gq) * 36 + k0 + tq]);
                af[i][1] = tfo(Ab[(m + gq + 8) * 36 + k0 + tq]);
                af[i][2] = tfo(Ab[(m + gq) * 36 + k0 + tq + 4]);
                af[i][3] = tfo(Ab[(m + gq + 8) * 36 + k0 + tq + 4]);
            }
#pragma unroll
            for (int j = 0; j < 2; j++) {
                const int n = warp_n + j * 8;
                uint32_t b1f[2] = { tfo(B1b[(k0 + tq) * 68 + n + gq]), tfo(B1b[(k0 + tq + 4) * 68 + n + gq]) };
                uint32_t b3f[2] = { tfo(B3b[(k0 + tq) * 68 + n + gq]), tfo(B3b[(k0 + tq + 4) * 68 + n + gq]) };
#pragma unroll
                for (int i = 0; i < 4; i++) {
                    mma8(accg[i][j], af[i], b1f);
                    mma8(accu[i][j], af[i], b3f);
                }
            }
        }
    }

    float* hb = g_h + ((size_t)e * T_TOK + m0) * H_DIM + n0;
#pragma unroll
    for (int i = 0; i < 4; i++) {
        const int r0 = warp_m + i * 16 + gq;
        const int r1 = r0 + 8;
#pragma unroll
        for (int j = 0; j < 2; j++) {
            const int col = warp_n + j * 8 + tq * 2;
            if (m0 + r0 < cnt) {
                float2 o;
                o.x = silu_mul(accg[i][j][0], accu[i][j][0]);
                o.y = silu_mul(accg[i][j][1], accu[i][j][1]);
                *(float2*)(hb + (size_t)r0 * H_DIM + col) = o;
            }
            if (m0 + r1 < cnt) {
                float2 o;
                o.x = silu_mul(accg[i][j][2], accu[i][j][2]);
                o.y = silu_mul(accg[i][j][3], accu[i][j][3]);
                *(float2*)(hb + (size_t)r1 * H_DIM + col) = o;
            }
        }
    }
}

// ---------------- gemm2: down = w_m * (H @ w2) ----------------
// BM=128, BN=128, BK=32. 8 warps (2M x 4N), warp tile 64x32.
__global__ __launch_bounds__(256, 2) void gemm2_mma(const float* __restrict__ w2){
    const int e = blockIdx.z, cnt = g_cnt[e], m0 = blockIdx.y * 128;
    if (m0 >= cnt) return;
    const int n0 = blockIdx.x * 128;

    const uint32_t sbase = smem_u32(dyn);
    const int tid = threadIdx.x, wid = tid >> 5, lane = tid & 31;
    const int gq = lane >> 2, tq = lane & 3;
    const int warp_m = (wid & 1) * 64, warp_n = (wid >> 1) * 32;

    // A staging: row tid>>1, k cols (tid&1)*16 + i*4
    const int arow = tid >> 1, ak0 = (tid & 1) * 16;
    const float* hA = g_h + ((size_t)e * T_TOK + min(m0 + arow, cnt - 1)) * H_DIM + ak0;
    const uint32_t dA = sbase + (uint32_t)(arow * 36 + ak0) * 4;

    // B staging: row tid>>3, cols (tid&7)*16 + i*4
    const int bkk = tid >> 3, bn0 = (tid & 7) * 16;
    const float* w2b = w2 + ((size_t)e * H_DIM + bkk) * D_DIM + n0 + bn0;
    const uint32_t dB = sbase + (uint32_t)(B2_OFF + bkk * 132 + bn0) * 4;

    float acc[4][4][4];
#pragma unroll
    for (int i = 0; i < 4; i++)
#pragma unroll
        for (int j = 0; j < 4; j++)
#pragma unroll
            for (int q = 0; q < 4; q++) acc[i][j][q] = 0.f;

    const int NC = H_DIM / 32;  // 88

    {
#pragma unroll
        for (int i = 0; i < 4; i++) cpa16(dA + i * 16, hA + i * 4);
#pragma unroll
        for (int i = 0; i < 4; i++) cpa16(dB + i * 16, w2b + i * 4);
        CP_COMMIT();
    }

    for (int c = 0; c < NC; c++) {
        CP_WAIT0();
        __syncthreads();

        if (c + 1 < NC) {
            const uint32_t bo = (uint32_t)(((c + 1) & 1) * BUF2_W) * 4;
            const int kg = (c + 1) * 32;
            const float* pB = w2b + (size_t)kg * D_DIM;
#pragma unroll
            for (int i = 0; i < 4; i++) cpa16(dA + bo + i * 16, hA + kg + i * 4);
#pragma unroll
            for (int i = 0; i < 4; i++) cpa16(dB + bo + i * 16, pB + i * 4);
        }
        CP_COMMIT();

        const uint32_t* Ab = dyn + (c & 1) * BUF2_W;
        const uint32_t* Bb = Ab + B2_OFF;

#pragma unroll
        for (int ks = 0; ks < 4; ks++) {
            const int k0 = ks * 8;
            uint32_t af[4][4];
#pragma unroll
            for (int i = 0; i < 4; i++) {
                const int m = warp_m + i * 16;
                af[i][0] = tfo(Ab[(m + gq) * 36 + k0 + tq]);
                af[i][1] = tfo(Ab[(m + gq + 8) * 36 + k0 + tq]);
                af[i][2] = tfo(Ab[(m + gq) * 36 + k0 + tq + 4]);
                af[i][3] = tfo(Ab[(m + gq + 8) * 36 + k0 + tq + 4]);
            }
#pragma unroll
            for (int j = 0; j < 4; j++) {
                const int n = warp_n + j * 8;
                uint32_t bf[2] = { tfo(Bb[(k0 + tq) * 132 + n + gq]), tfo(Bb[(k0 + tq + 4) * 132 + n + gq]) };
#pragma unroll
                for (int i = 0; i < 4; i++) mma8(acc[i][j], af[i], bf);
            }
        }
    }

    float* db = g_down + ((size_t)e * T_TOK + m0) * D_DIM + n0;
#pragma unroll
    for (int i = 0; i < 4; i++) {
        const int r0 = warp_m + i * 16 + gq;
        const int r1 = r0 + 8;
        const float wg0 = g_slot_w[e * T_TOK + min(m0 + r0, cnt - 1)];
        const float wg1 = g_slot_w[e * T_TOK + min(m0 + r1, cnt - 1)];
#pragma unroll
        for (int j = 0; j < 4; j++) {
            const int col = warp_n + j * 8 + tq * 2;
            if (m0 + r0 < cnt) {
                float2 o; o.x = acc[i][j][0] * wg0; o.y = acc[i][j][1] * wg0;
                *(float2*)(db + (size_t)r0 * D_DIM + col) = o;
            }
            if (m0 + r1 < cnt) {
                float2 o; o.x = acc[i][j][2] * wg1; o.y = acc[i][j][3] * wg1;
                *(float2*)(db + (size_t)r1 * D_DIM + col) = o;
            }
        }
    }
}

// ---------------- launch ----------------
extern "C" void kernel_launch(void* const* d_in, const int* in_sizes, int n_in,
                              void* d_out, int out_size){
    const float* x  = (const float*)d_in[0];
    const float* wg = (const float*)d_in[1];
    const float* w1 = (const float*)d_in[2];
    const float* w2 = (const float*)d_in[3];
    const float* w3 = (const float*)d_in[4];
    float* out = (float*)d_out;

    const int smem13 = 2 * BUF13_W * 4;  // 71680
    const int smem2  = 2 * BUF2_W * 4;   // 70656
    cudaFuncSetAttribute(gemm13_mma, cudaFuncAttributeMaxDynamicSharedMemorySize, smem13);
    cudaFuncSetAttribute(gemm2_mma,  cudaFuncAttributeMaxDynamicSharedMemorySize, smem2);

    zero_cnt_kernel<<<1, 32>>>();
    gating_kernel<<<T_TOK, 256>>>(x, wg);
    gemm13_mma<<<dim3(H_DIM / 64, T_TOK / 128, E_NUM), 256, smem13>>>(x, w1, w3);
    gemm2_mma<<<dim3(D_DIM / 128, T_TOK / 128, E_NUM), 256, smem2>>>(w2);
    combine_kernel<<<T_TOK, 256>>>(out);
}

// round 8
// speedup vs baseline: 1.2765x; 1.2765x over previous
#include <cuda_runtime.h>
#include <math.h>
#include <stdint.h>

#define T_TOK 4096
#define D_DIM 1024
#define E_NUM 8
#define H_DIM 2816

__device__ int   g_cnt[E_NUM];
__device__ int   g_slot_tok[E_NUM * T_TOK];
__device__ float g_slot_w[E_NUM * T_TOK];
__device__ int   g_tok_slot[T_TOK * 2];
__device__ float g_h[(size_t)E_NUM * T_TOK * H_DIM];
__device__ float g_down[(size_t)E_NUM * T_TOK * D_DIM];
// tf32-pre-rounded copies
__device__ float g_xc[(size_t)T_TOK * D_DIM];
__device__ float g_w1c[(size_t)E_NUM * D_DIM * H_DIM];
__device__ float g_w3c[(size_t)E_NUM * D_DIM * H_DIM];
__device__ float g_w2c[(size_t)E_NUM * H_DIM * D_DIM];

// ---------------- helpers ----------------
__device__ __forceinline__ uint32_t smem_u32(const void* p){
    uint32_t a; asm("{ .reg .u64 t; cvta.to.shared.u64 t, %1; cvt.u32.u64 %0, t; }" : "=r"(a) : "l"(p)); return a;
}
__device__ __forceinline__ float tf32f(float f){
    uint32_t r; asm("cvt.rna.tf32.f32 %0, %1;" : "=r"(r) : "f"(f)); return __uint_as_float(r);
}
__device__ __forceinline__ void mma8(float* c, const uint32_t* a, const uint32_t* b){
    asm volatile("mma.sync.aligned.m16n8k8.row.col.f32.tf32.tf32.f32 "
        "{%0,%1,%2,%3}, {%4,%5,%6,%7}, {%8,%9}, {%0,%1,%2,%3};"
        : "+f"(c[0]), "+f"(c[1]), "+f"(c[2]), "+f"(c[3])
        : "r"(a[0]), "r"(a[1]), "r"(a[2]), "r"(a[3]), "r"(b[0]), "r"(b[1]));
}
__device__ __forceinline__ void ldsm4(uint32_t* r, uint32_t addr){
    asm volatile("ldmatrix.sync.aligned.m8n8.x4.shared.b16 {%0,%1,%2,%3}, [%4];"
        : "=r"(r[0]), "=r"(r[1]), "=r"(r[2]), "=r"(r[3]) : "r"(addr));
}
__device__ __forceinline__ float silu_mul(float g, float u){
    return (g / (1.f + expf(-g))) * u;
}
__device__ __forceinline__ void cpa16(uint32_t dst, const void* src){
    asm volatile("cp.async.cg.shared.global [%0], [%1], 16;" :: "r"(dst), "l"(src) : "memory");
}
#define CP_COMMIT() asm volatile("cp.async.commit_group;" ::: "memory")
#define CP_WAIT0()  asm volatile("cp.async.wait_group 0;" ::: "memory")

// ---------------- small kernels ----------------
__global__ void zero_cnt_kernel() { if (threadIdx.x < E_NUM) g_cnt[threadIdx.x] = 0; }

// elementwise tf32 pre-round (float4 granular)
__global__ __launch_bounds__(256) void cvt_tf32_kernel(const float4* __restrict__ src,
                                                       float4* __restrict__ dst, int n4){
    const int i = blockIdx.x * 256 + threadIdx.x;
    if (i < n4) {
        float4 v = src[i];
        float4 o;
        o.x = tf32f(v.x); o.y = tf32f(v.y); o.z = tf32f(v.z); o.w = tf32f(v.w);
        dst[i] = o;
    }
}

__global__ __launch_bounds__(256) void gating_kernel(const float* __restrict__ x,
                                                     const float* __restrict__ wg){
    __shared__ float s_red[E_NUM][256];
    const int t = blockIdx.x, tid = threadIdx.x;
    const float* xr = x + (size_t)t * D_DIM;
    float part[E_NUM];
#pragma unroll
    for (int e = 0; e < E_NUM; e++) part[e] = 0.f;
    for (int d = tid; d < D_DIM; d += 256) {
        const float xv = xr[d];
        const float* w = wg + (size_t)d * E_NUM;
#pragma unroll
        for (int e = 0; e < E_NUM; e++) part[e] += xv * w[e];
    }
#pragma unroll
    for (int e = 0; e < E_NUM; e++) s_red[e][tid] = part[e];
    __syncthreads();
    for (int s = 128; s > 0; s >>= 1) {
        if (tid < s) {
#pragma unroll
            for (int e = 0; e < E_NUM; e++) s_red[e][tid] += s_red[e][tid + s];
        }
        __syncthreads();
    }
    if (tid == 0) {
        float p[E_NUM]; float mx = -1e30f;
#pragma unroll
        for (int e = 0; e < E_NUM; e++) mx = fmaxf(mx, s_red[e][0]);
#pragma unroll
        for (int e = 0; e < E_NUM; e++) p[e] = expf(s_red[e][0] - mx);
        int i1 = 0;
#pragma unroll
        for (int e = 1; e < E_NUM; e++) if (p[e] > p[i1]) i1 = e;
        int i2 = (i1 == 0) ? 1 : 0;
#pragma unroll
        for (int e = 0; e < E_NUM; e++) if (e != i1 && p[e] > p[i2]) i2 = e;
        const float ws = p[i1] + p[i2];
        const int s0 = atomicAdd(&g_cnt[i1], 1);
        const int s1 = atomicAdd(&g_cnt[i2], 1);
        g_slot_tok[i1 * T_TOK + s0] = t;  g_slot_w[i1 * T_TOK + s0] = p[i1] / ws;
        g_slot_tok[i2 * T_TOK + s1] = t;  g_slot_w[i2 * T_TOK + s1] = p[i2] / ws;
        g_tok_slot[2 * t + 0] = i1 * T_TOK + s0;
        g_tok_slot[2 * t + 1] = i2 * T_TOK + s1;
    }
}

__global__ __launch_bounds__(256) void combine_kernel(float* __restrict__ out){
    const int t = blockIdx.x, i = threadIdx.x;
    const int s0 = g_tok_slot[2 * t + 0], s1 = g_tok_slot[2 * t + 1];
    const float4 a = *(const float4*)(g_down + (size_t)s0 * D_DIM + i * 4);
    const float4 b = *(const float4*)(g_down + (size_t)s1 * D_DIM + i * 4);
    float4 o; o.x = a.x + b.x; o.y = a.y + b.y; o.z = a.z + b.z; o.w = a.w + b.w;
    *(float4*)(out + (size_t)t * D_DIM + i * 4) = o;
}

// Dynamic SMEM layouts (uint32 words):
// gemm13 per buffer: A[128][36] (4608) | B1[32][68] (2176) | B3[32][68] (2176) = 8960 words
// gemm2  per buffer: A[128][36] (4608) | B[32][132] (4224)                     = 8832 words
#define BUF13_W 8960
#define B1_OFF  4608
#define B3_OFF  6784
#define BUF2_W  8832
#define B2_OFF  4608

extern __shared__ uint32_t dyn[];

// ---------------- gemm13: h = silu(X@w1) * (X@w3) ----------------
// BM=128, BN=64 per matrix, BK=32. 4 warps (2M x 2N), warp tile 64x32 per matrix.
__global__ __launch_bounds__(128, 2) void gemm13_mma(){
    const int e = blockIdx.z, cnt = g_cnt[e], m0 = blockIdx.y * 128;
    if (m0 >= cnt) return;
    const int n0 = blockIdx.x * 64;

    __shared__ int s_row[128];
    const uint32_t sbase = smem_u32(dyn);

    const int tid = threadIdx.x, wid = tid >> 5, lane = tid & 31;
    const int gq = lane >> 2, tq = lane & 3;
    const int warp_m = (wid & 1) * 64, warp_n = (wid >> 1) * 32;

    s_row[tid] = g_slot_tok[e * T_TOK + min(m0 + tid, cnt - 1)];
    __syncthreads();

    // A staging: thread rows arow+rr*32, k cols ak0..ak0+7
    const int arow = tid >> 2, ak0 = (tid & 3) * 8;
    const float* xA[4];
#pragma unroll
    for (int rr = 0; rr < 4; rr++)
        xA[rr] = g_xc + (size_t)s_row[arow + rr * 32] * D_DIM + ak0;
    const uint32_t dA = sbase + (uint32_t)(arow * 36 + ak0) * 4;

    // B staging: k rows bkk, bkk+16; cols bn0..bn0+7 (both matrices)
    const int bkk = tid >> 3, bn0 = (tid & 7) * 8;
    const float* w1b = g_w1c + ((size_t)e * D_DIM + bkk) * H_DIM + n0 + bn0;
    const float* w3b = g_w3c + ((size_t)e * D_DIM + bkk) * H_DIM + n0 + bn0;
    const uint32_t dB1 = sbase + (uint32_t)(B1_OFF + bkk * 68 + bn0) * 4;
    const uint32_t dB3 = sbase + (uint32_t)(B3_OFF + bkk * 68 + bn0) * 4;

    // ldmatrix per-lane byte offsets within buffer, for m-tiles i=0..3
    const int lrow = (lane & 7) + ((lane >> 3) & 1) * 8;
    const int lkw = ((lane >> 4) & 1) * 4;
    uint32_t a_off[4];
#pragma unroll
    for (int i = 0; i < 4; i++)
        a_off[i] = (uint32_t)(((warp_m + i * 16 + lrow) * 36 + lkw) * 4);

    float accg[4][4][4], accu[4][4][4];
#pragma unroll
    for (int i = 0; i < 4; i++)
#pragma unroll
        for (int j = 0; j < 4; j++)
#pragma unroll
            for (int q = 0; q < 4; q++) { accg[i][j][q] = 0.f; accu[i][j][q] = 0.f; }

    const int NC = D_DIM / 32;

    // prologue fill chunk 0
    {
#pragma unroll
        for (int rr = 0; rr < 4; rr++) {
            cpa16(dA + rr * (32 * 36 * 4),      xA[rr]);
            cpa16(dA + rr * (32 * 36 * 4) + 16, xA[rr] + 4);
        }
#pragma unroll
        for (int pp = 0; pp < 2; pp++) {
            const float* p1 = w1b + (size_t)(pp * 16) * H_DIM;
            const float* p3 = w3b + (size_t)(pp * 16) * H_DIM;
            cpa16(dB1 + pp * (16 * 68 * 4),      p1);
            cpa16(dB1 + pp * (16 * 68 * 4) + 16, p1 + 4);
            cpa16(dB3 + pp * (16 * 68 * 4),      p3);
            cpa16(dB3 + pp * (16 * 68 * 4) + 16, p3 + 4);
        }
        CP_COMMIT();
    }

    for (int c = 0; c < NC; c++) {
        CP_WAIT0();
        __syncthreads();

        if (c + 1 < NC) {
            const uint32_t bo = (uint32_t)(((c + 1) & 1) * BUF13_W) * 4;
            const int kg = (c + 1) * 32;
#pragma unroll
            for (int rr = 0; rr < 4; rr++) {
                cpa16(dA + bo + rr * (32 * 36 * 4),      xA[rr] + kg);
                cpa16(dA + bo + rr * (32 * 36 * 4) + 16, xA[rr] + kg + 4);
            }
#pragma unroll
            for (int pp = 0; pp < 2; pp++) {
                const float* p1 = w1b + (size_t)(kg + pp * 16) * H_DIM;
                const float* p3 = w3b + (size_t)(kg + pp * 16) * H_DIM;
                cpa16(dB1 + bo + pp * (16 * 68 * 4),      p1);
                cpa16(dB1 + bo + pp * (16 * 68 * 4) + 16, p1 + 4);
                cpa16(dB3 + bo + pp * (16 * 68 * 4),      p3);
                cpa16(dB3 + bo + pp * (16 * 68 * 4) + 16, p3 + 4);
            }
        }
        CP_COMMIT();

        const uint32_t abuf = sbase + (uint32_t)((c & 1) * BUF13_W) * 4;
        const uint32_t* Ab  = dyn + (c & 1) * BUF13_W;
        const uint32_t* B1b = Ab + B1_OFF;
        const uint32_t* B3b = Ab + B3_OFF;

        uint32_t af[2][4][4], b1f[2][4][2], b3f[2][4][2];
        // ks=0 fragments
#pragma unroll
        for (int i = 0; i < 4; i++) ldsm4(af[0][i], abuf + a_off[i]);
#pragma unroll
        for (int j = 0; j < 4; j++) {
            const int n = warp_n + j * 8 + gq;
            b1f[0][j][0] = B1b[tq * 68 + n];       b1f[0][j][1] = B1b[(tq + 4) * 68 + n];
            b3f[0][j][0] = B3b[tq * 68 + n];       b3f[0][j][1] = B3b[(tq + 4) * 68 + n];
        }
#pragma unroll
        for (int ks = 0; ks < 4; ks++) {
            const int cur = ks & 1, nxt = cur ^ 1;
            if (ks < 3) {
                const int k1 = (ks + 1) * 8;
#pragma unroll
                for (int i = 0; i < 4; i++) ldsm4(af[nxt][i], abuf + a_off[i] + (ks + 1) * 32);
#pragma unroll
                for (int j = 0; j < 4; j++) {
                    const int n = warp_n + j * 8 + gq;
                    b1f[nxt][j][0] = B1b[(k1 + tq) * 68 + n];     b1f[nxt][j][1] = B1b[(k1 + tq + 4) * 68 + n];
                    b3f[nxt][j][0] = B3b[(k1 + tq) * 68 + n];     b3f[nxt][j][1] = B3b[(k1 + tq + 4) * 68 + n];
                }
            }
#pragma unroll
            for (int j = 0; j < 4; j++)
#pragma unroll
                for (int i = 0; i < 4; i++) {
                    mma8(accg[i][j], af[cur][i], b1f[cur][j]);
                    mma8(accu[i][j], af[cur][i], b3f[cur][j]);
                }
        }
    }

    // epilogue: h = silu(gate)*up, tf32-rounded, -> g_h
    float* hb = g_h + ((size_t)e * T_TOK + m0) * H_DIM + n0;
#pragma unroll
    for (int i = 0; i < 4; i++) {
        const int r0 = warp_m + i * 16 + gq;
        const int r1 = r0 + 8;
#pragma unroll
        for (int j = 0; j < 4; j++) {
            const int col = warp_n + j * 8 + tq * 2;
            if (m0 + r0 < cnt) {
                float2 o;
                o.x = tf32f(silu_mul(accg[i][j][0], accu[i][j][0]));
                o.y = tf32f(silu_mul(accg[i][j][1], accu[i][j][1]));
                *(float2*)(hb + (size_t)r0 * H_DIM + col) = o;
            }
            if (m0 + r1 < cnt) {
                float2 o;
                o.x = tf32f(silu_mul(accg[i][j][2], accu[i][j][2]));
                o.y = tf32f(silu_mul(accg[i][j][3], accu[i][j][3]));
                *(float2*)(hb + (size_t)r1 * H_DIM + col) = o;
            }
        }
    }
}

// ---------------- gemm2: down = w_m * (H @ w2) ----------------
// BM=128, BN=128, BK=32. 4 warps (2M x 2N), warp tile 64x64.
__global__ __launch_bounds__(128, 2) void gemm2_mma(){
    const int e = blockIdx.z, cnt = g_cnt[e], m0 = blockIdx.y * 128;
    if (m0 >= cnt) return;
    const int n0 = blockIdx.x * 128;

    const uint32_t sbase = smem_u32(dyn);
    const int tid = threadIdx.x, wid = tid >> 5, lane = tid & 31;
    const int gq = lane >> 2, tq = lane & 3;
    const int warp_m = (wid & 1) * 64, warp_n = (wid >> 1) * 64;

    const int arow = tid >> 2, ak0 = (tid & 3) * 8;
    const float* hA[4];
#pragma unroll
    for (int rr = 0; rr < 4; rr++)
        hA[rr] = g_h + ((size_t)e * T_TOK + min(m0 + arow + rr * 32, cnt - 1)) * H_DIM + ak0;
    const uint32_t dA = sbase + (uint32_t)(arow * 36 + ak0) * 4;

    const int bkk = tid >> 3, bn0 = (tid & 7) * 16;
    const float* w2b = g_w2c + ((size_t)e * H_DIM + bkk) * D_DIM + n0 + bn0;
    const uint32_t dB = sbase + (uint32_t)(B2_OFF + bkk * 132 + bn0) * 4;

    const int lrow = (lane & 7) + ((lane >> 3) & 1) * 8;
    const int lkw = ((lane >> 4) & 1) * 4;
    uint32_t a_off[4];
#pragma unroll
    for (int i = 0; i < 4; i++)
        a_off[i] = (uint32_t)(((warp_m + i * 16 + lrow) * 36 + lkw) * 4);

    float acc[4][8][4];
#pragma unroll
    for (int i = 0; i < 4; i++)
#pragma unroll
        for (int j = 0; j < 8; j++)
#pragma unroll
            for (int q = 0; q < 4; q++) acc[i][j][q] = 0.f;

    const int NC = H_DIM / 32;  // 88

    {
#pragma unroll
        for (int rr = 0; rr < 4; rr++) {
            cpa16(dA + rr * (32 * 36 * 4),      hA[rr]);
            cpa16(dA + rr * (32 * 36 * 4) + 16, hA[rr] + 4);
        }
#pragma unroll
        for (int pp = 0; pp < 2; pp++) {
            const float* p = w2b + (size_t)(pp * 16) * D_DIM;
#pragma unroll
            for (int i = 0; i < 4; i++)
                cpa16(dB + pp * (16 * 132 * 4) + i * 16, p + i * 4);
        }
        CP_COMMIT();
    }

    for (int c = 0; c < NC; c++) {
        CP_WAIT0();
        __syncthreads();

        if (c + 1 < NC) {
            const uint32_t bo = (uint32_t)(((c + 1) & 1) * BUF2_W) * 4;
            const int kg = (c + 1) * 32;
#pragma unroll
            for (int rr = 0; rr < 4; rr++) {
                cpa16(dA + bo + rr * (32 * 36 * 4),      hA[rr] + kg);
                cpa16(dA + bo + rr * (32 * 36 * 4) + 16, hA[rr] + kg + 4);
            }
#pragma unroll
            for (int pp = 0; pp < 2; pp++) {
                const float* p = w2b + (size_t)(kg + pp * 16) * D_DIM;
#pragma unroll
                for (int i = 0; i < 4; i++)
                    cpa16(dB + bo + pp * (16 * 132 * 4) + i * 16, p + i * 4);
            }
        }
        CP_COMMIT();

        const uint32_t abuf = sbase + (uint32_t)((c & 1) * BUF2_W) * 4;
        const uint32_t* Ab = dyn + (c & 1) * BUF2_W;
        const uint32_t* Bb = Ab + B2_OFF;

        uint32_t af[2][4][4], bf[2][8][2];
#pragma unroll
        for (int i = 0; i < 4; i++) ldsm4(af[0][i], abuf + a_off[i]);
#pragma unroll
        for (int j = 0; j < 8; j++) {
            const int n = warp_n + j * 8 + gq;
            bf[0][j][0] = Bb[tq * 132 + n];       bf[0][j][1] = Bb[(tq + 4) * 132 + n];
        }
#pragma unroll
        for (int ks = 0; ks < 4; ks++) {
            const int cur = ks & 1, nxt = cur ^ 1;
            if (ks < 3) {
                const int k1 = (ks + 1) * 8;
#pragma unroll
                for (int i = 0; i < 4; i++) ldsm4(af[nxt][i], abuf + a_off[i] + (ks + 1) * 32);
#pragma unroll
                for (int j = 0; j < 8; j++) {
                    const int n = warp_n + j * 8 + gq;
                    bf[nxt][j][0] = Bb[(k1 + tq) * 132 + n];
                    bf[nxt][j][1] = Bb[(k1 + tq + 4) * 132 + n];
                }
            }
#pragma unroll
            for (int j = 0; j < 8; j++)
#pragma unroll
                for (int i = 0; i < 4; i++) mma8(acc[i][j], af[cur][i], bf[cur][j]);
        }
    }

    float* db = g_down + ((size_t)e * T_TOK + m0) * D_DIM + n0;
#pragma unroll
    for (int i = 0; i < 4; i++) {
        const int r0 = warp_m + i * 16 + gq;
        const int r1 = r0 + 8;
        const float wg0 = g_slot_w[e * T_TOK + min(m0 + r0, cnt - 1)];
        const float wg1 = g_slot_w[e * T_TOK + min(m0 + r1, cnt - 1)];
#pragma unroll
        for (int j = 0; j < 8; j++) {
            const int col = warp_n + j * 8 + tq * 2;
            if (m0 + r0 < cnt) {
                float2 o; o.x = acc[i][j][0] * wg0; o.y = acc[i][j][1] * wg0;
                *(float2*)(db + (size_t)r0 * D_DIM + col) = o;
            }
            if (m0 + r1 < cnt) {
                float2 o; o.x = acc[i][j][2] * wg1; o.y = acc[i][j][3] * wg1;
                *(float2*)(db + (size_t)r1 * D_DIM + col) = o;
            }
        }
    }
}

// ---------------- launch ----------------
extern "C" void kernel_launch(void* const* d_in, const int* in_sizes, int n_in,
                              void* d_out, int out_size){
    const float* x  = (const float*)d_in[0];
    const float* wg = (const float*)d_in[1];
    const float* w1 = (const float*)d_in[2];
    const float* w2 = (const float*)d_in[3];
    const float* w3 = (const float*)d_in[4];
    float* out = (float*)d_out;

    const int smem13 = 2 * BUF13_W * 4;  // 71680
    const int smem2  = 2 * BUF2_W * 4;   // 70656
    cudaFuncSetAttribute(gemm13_mma, cudaFuncAttributeMaxDynamicSharedMemorySize, smem13);
    cudaFuncSetAttribute(gemm2_mma,  cudaFuncAttributeMaxDynamicSharedMemorySize, smem2);

    float* xc;  cudaGetSymbolAddress((void**)&xc,  g_xc);
    float* w1c; cudaGetSymbolAddress((void**)&w1c, g_w1c);
    float* w3c; cudaGetSymbolAddress((void**)&w3c, g_w3c);
    float* w2c; cudaGetSymbolAddress((void**)&w2c, g_w2c);

    const int nw4 = (E_NUM * D_DIM * H_DIM) / 4;   // 5767168
    const int nx4 = (T_TOK * D_DIM) / 4;           // 1048576

    zero_cnt_kernel<<<1, 32>>>();
    gating_kernel<<<T_TOK, 256>>>(x, wg);
    cvt_tf32_kernel<<<(nx4 + 255) / 256, 256>>>((const float4*)x,  (float4*)xc,  nx4);
    cvt_tf32_kernel<<<(nw4 + 255) / 256, 256>>>((const float4*)w1, (float4*)w1c, nw4);
    cvt_tf32_kernel<<<(nw4 + 255) / 256, 256>>>((const float4*)w3, (float4*)w3c, nw4);
    cvt_tf32_kernel<<<(nw4 + 255) / 256, 256>>>((const float4*)w2, (float4*)w2c, nw4);
    gemm13_mma<<<dim3(H_DIM / 64, T_TOK / 128, E_NUM), 128, smem13>>>();
    gemm2_mma<<<dim3(D_DIM / 128, T_TOK / 128, E_NUM), 128, smem2>>>();
    combine_kernel<<<T_TOK, 256>>>(out);
}

// round 9
// speedup vs baseline: 1.6649x; 1.3043x over previous
#include <cuda_runtime.h>
#include <cuda_fp16.h>
#include <math.h>
#include <stdint.h>

#define T_TOK 4096
#define D_DIM 1024
#define E_NUM 8
#define H_DIM 2816
#define KC 64

__device__ int   g_cnt[E_NUM];
__device__ int   g_slot_tok[E_NUM * T_TOK];
__device__ float g_slot_w[E_NUM * T_TOK];
__device__ int   g_tok_slot[T_TOK * 2];
__device__ float g_down[(size_t)E_NUM * T_TOK * D_DIM];
// fp16 copies / activations
__device__ __half g_xh[(size_t)T_TOK * D_DIM];
__device__ __half g_w1h[(size_t)E_NUM * D_DIM * H_DIM];
__device__ __half g_w3h[(size_t)E_NUM * D_DIM * H_DIM];
__device__ __half g_w2h[(size_t)E_NUM * H_DIM * D_DIM];
__device__ __half g_hh[(size_t)E_NUM * T_TOK * H_DIM];

// ---------------- helpers ----------------
__device__ __forceinline__ uint32_t smem_u32(const void* p){
    uint32_t a; asm("{ .reg .u64 t; cvta.to.shared.u64 t, %1; cvt.u32.u64 %0, t; }" : "=r"(a) : "l"(p)); return a;
}
__device__ __forceinline__ void mma16(float* c, const uint32_t* a, const uint32_t* b){
    asm volatile("mma.sync.aligned.m16n8k16.row.col.f32.f16.f16.f32 "
        "{%0,%1,%2,%3}, {%4,%5,%6,%7}, {%8,%9}, {%0,%1,%2,%3};"
        : "+f"(c[0]), "+f"(c[1]), "+f"(c[2]), "+f"(c[3])
        : "r"(a[0]), "r"(a[1]), "r"(a[2]), "r"(a[3]), "r"(b[0]), "r"(b[1]));
}
__device__ __forceinline__ void ldsm4(uint32_t* r, uint32_t addr){
    asm volatile("ldmatrix.sync.aligned.m8n8.x4.shared.b16 {%0,%1,%2,%3}, [%4];"
        : "=r"(r[0]), "=r"(r[1]), "=r"(r[2]), "=r"(r[3]) : "r"(addr));
}
__device__ __forceinline__ void ldsm4t(uint32_t* r, uint32_t addr){
    asm volatile("ldmatrix.sync.aligned.m8n8.x4.trans.shared.b16 {%0,%1,%2,%3}, [%4];"
        : "=r"(r[0]), "=r"(r[1]), "=r"(r[2]), "=r"(r[3]) : "r"(addr));
}
__device__ __forceinline__ float silu_mul(float g, float u){
    return (g / (1.f + expf(-g))) * u;
}
__device__ __forceinline__ void cpa16(uint32_t dst, const void* src){
    asm volatile("cp.async.cg.shared.global [%0], [%1], 16;" :: "r"(dst), "l"(src) : "memory");
}
#define CP_COMMIT() asm volatile("cp.async.commit_group;" ::: "memory")
#define CP_WAIT1()  asm volatile("cp.async.wait_group 1;" ::: "memory")

// ---------------- small kernels ----------------
__global__ void zero_cnt_kernel() { if (threadIdx.x < E_NUM) g_cnt[threadIdx.x] = 0; }

// fp32 -> fp16 pre-round, 8 elements/thread
__global__ __launch_bounds__(256) void cvt_f16_kernel(const float* __restrict__ src,
                                                      __half* __restrict__ dst, int n8){
    const int i = blockIdx.x * 256 + threadIdx.x;
    if (i < n8) {
        const float4* s4 = (const float4*)src + 2 * (size_t)i;
        float4 a = s4[0], b = s4[1];
        half2 h0 = __floats2half2_rn(a.x, a.y);
        half2 h1 = __floats2half2_rn(a.z, a.w);
        half2 h2 = __floats2half2_rn(b.x, b.y);
        half2 h3 = __floats2half2_rn(b.z, b.w);
        uint4 o;
        o.x = *(uint32_t*)&h0; o.y = *(uint32_t*)&h1;
        o.z = *(uint32_t*)&h2; o.w = *(uint32_t*)&h3;
        *(uint4*)(dst + 8 * (size_t)i) = o;
    }
}

__global__ __launch_bounds__(256) void gating_kernel(const float* __restrict__ x,
                                                     const float* __restrict__ wg){
    __shared__ float s_red[E_NUM][256];
    const int t = blockIdx.x, tid = threadIdx.x;
    const float* xr = x + (size_t)t * D_DIM;
    float part[E_NUM];
#pragma unroll
    for (int e = 0; e < E_NUM; e++) part[e] = 0.f;
    for (int d = tid; d < D_DIM; d += 256) {
        const float xv = xr[d];
        const float* w = wg + (size_t)d * E_NUM;
#pragma unroll
        for (int e = 0; e < E_NUM; e++) part[e] += xv * w[e];
    }
#pragma unroll
    for (int e = 0; e < E_NUM; e++) s_red[e][tid] = part[e];
    __syncthreads();
    for (int s = 128; s > 0; s >>= 1) {
        if (tid < s) {
#pragma unroll
            for (int e = 0; e < E_NUM; e++) s_red[e][tid] += s_red[e][tid + s];
        }
        __syncthreads();
    }
    if (tid == 0) {
        float p[E_NUM]; float mx = -1e30f;
#pragma unroll
        for (int e = 0; e < E_NUM; e++) mx = fmaxf(mx, s_red[e][0]);
#pragma unroll
        for (int e = 0; e < E_NUM; e++) p[e] = expf(s_red[e][0] - mx);
        int i1 = 0;
#pragma unroll
        for (int e = 1; e < E_NUM; e++) if (p[e] > p[i1]) i1 = e;
        int i2 = (i1 == 0) ? 1 : 0;
#pragma unroll
        for (int e = 0; e < E_NUM; e++) if (e != i1 && p[e] > p[i2]) i2 = e;
        const float ws = p[i1] + p[i2];
        const int s0 = atomicAdd(&g_cnt[i1], 1);
        const int s1 = atomicAdd(&g_cnt[i2], 1);
        g_slot_tok[i1 * T_TOK + s0] = t;  g_slot_w[i1 * T_TOK + s0] = p[i1] / ws;
        g_slot_tok[i2 * T_TOK + s1] = t;  g_slot_w[i2 * T_TOK + s1] = p[i2] / ws;
        g_tok_slot[2 * t + 0] = i1 * T_TOK + s0;
        g_tok_slot[2 * t + 1] = i2 * T_TOK + s1;
    }
}

__global__ __launch_bounds__(256) void combine_kernel(float* __restrict__ out){
    const int t = blockIdx.x, i = threadIdx.x;
    const int s0 = g_tok_slot[2 * t + 0], s1 = g_tok_slot[2 * t + 1];
    const float4 a = *(const float4*)(g_down + (size_t)s0 * D_DIM + i * 4);
    const float4 b = *(const float4*)(g_down + (size_t)s1 * D_DIM + i * 4);
    float4 o; o.x = a.x + b.x; o.y = a.y + b.y; o.z = a.z + b.z; o.w = a.w + b.w;
    *(float4*)(out + (size_t)t * D_DIM + i * 4) = o;
}

// SMEM layouts in halves. A[128][72] rows pitch 144B (bank step 4, conflict-free ldsm).
// gemm13: A(9216) | B1[64][72](4608) | B3[64][72](4608)  -> 18432 halves = 36864 B/buf
// gemm2 : A(9216) | B[64][136](8704)                      -> 17920 halves = 35840 B/buf
#define BUFB13 36864
#define B1OFFB 18432
#define B3OFFB 27648
#define BUFB2  35840
#define B2OFFB 18432

extern __shared__ uint32_t dyn[];

// ---------------- gemm13: h = silu(X@w1)*(X@w3). BM=128,BN=64/matrix,KC=64.
// 4 warps (2M x 2N), warp tile 64m x 32n per matrix. 3-stage cp.async pipeline.
__global__ __launch_bounds__(128, 2) void gemm13_mma(){
    const int e = blockIdx.z, cnt = g_cnt[e], m0 = blockIdx.y * 128;
    if (m0 >= cnt) return;
    const int n0 = blockIdx.x * 64;

    __shared__ int s_row[128];
    const uint32_t sbase = smem_u32(dyn);
    const int tid = threadIdx.x, wid = tid >> 5, lane = tid & 31;
    const int gq = lane >> 2, tq = lane & 3;
    const int warp_m = (wid & 1) * 64, warp_n = (wid >> 1) * 32;

    s_row[tid] = g_slot_tok[e * T_TOK + min(m0 + tid, cnt - 1)];
    __syncthreads();

    const __half* xs  = g_xh + (size_t)s_row[tid] * D_DIM;            // + kg
    const int brow = tid >> 1, bhw = (tid & 1) * 32;
    const __half* w1s = g_w1h + ((size_t)e * D_DIM + brow) * H_DIM + n0 + bhw;  // + kg*H
    const __half* w3s = g_w3h + ((size_t)e * D_DIM + brow) * H_DIM + n0 + bhw;
    const uint32_t dA  = sbase + (uint32_t)tid * 144u;
    const uint32_t dB1 = sbase + B1OFFB + (uint32_t)(brow * 144 + bhw * 2);
    const uint32_t dB3 = sbase + B3OFFB + (uint32_t)(brow * 144 + bhw * 2);

    auto fill = [&](int c){
        const uint32_t bo = (uint32_t)(c % 3) * BUFB13;
        const int kg = c * KC;
        const __half* pa = xs + kg;
#pragma unroll
        for (int i = 0; i < 8; i++) cpa16(dA + bo + i * 16, pa + i * 8);
        const __half* p1 = w1s + (size_t)kg * H_DIM;
        const __half* p3 = w3s + (size_t)kg * H_DIM;
#pragma unroll
        for (int i = 0; i < 4; i++) cpa16(dB1 + bo + i * 16, p1 + i * 8);
#pragma unroll
        for (int i = 0; i < 4; i++) cpa16(dB3 + bo + i * 16, p3 + i * 8);
    };

    // ldmatrix lane offsets (bytes)
    uint32_t a_off[4];
#pragma unroll
    for (int i = 0; i < 4; i++)
        a_off[i] = (uint32_t)(((warp_m + i * 16 + (lane & 15)) * 72 + (lane >> 4) * 8) * 2);
    uint32_t b_off[2];
#pragma unroll
    for (int p = 0; p < 2; p++)
        b_off[p] = (uint32_t)(B1OFFB + ((lane & 15) * 72 + warp_n + p * 16 + (lane >> 4) * 8) * 2);

    float accg[4][4][4], accu[4][4][4];
#pragma unroll
    for (int i = 0; i < 4; i++)
#pragma unroll
        for (int j = 0; j < 4; j++)
#pragma unroll
            for (int q = 0; q < 4; q++) { accg[i][j][q] = 0.f; accu[i][j][q] = 0.f; }

    const int NC = D_DIM / KC;  // 16
    fill(0); CP_COMMIT();
    fill(1); CP_COMMIT();

    for (int c = 0; c < NC; c++) {
        CP_WAIT1();
        __syncthreads();
        if (c + 2 < NC) fill(c + 2);
        CP_COMMIT();

        const uint32_t abuf = sbase + (uint32_t)(c % 3) * BUFB13;
        uint32_t af[2][4][4], b1f[2][4][2], b3f[2][4][2];

        auto ldfr = [&](int ks, int buf){
#pragma unroll
            for (int i = 0; i < 4; i++) ldsm4(af[buf][i], abuf + a_off[i] + ks * 32);
#pragma unroll
            for (int p = 0; p < 2; p++) {
                uint32_t d[4];
                ldsm4t(d, abuf + b_off[p] + ks * 2304);
                b1f[buf][2*p][0] = d[0]; b1f[buf][2*p][1] = d[1];
                b1f[buf][2*p+1][0] = d[2]; b1f[buf][2*p+1][1] = d[3];
                ldsm4t(d, abuf + b_off[p] + 9216 + ks * 2304);
                b3f[buf][2*p][0] = d[0]; b3f[buf][2*p][1] = d[1];
                b3f[buf][2*p+1][0] = d[2]; b3f[buf][2*p+1][1] = d[3];
            }
        };
        ldfr(0, 0);
#pragma unroll
        for (int ks = 0; ks < 4; ks++) {
            const int cur = ks & 1, nxt = cur ^ 1;
            if (ks < 3) ldfr(ks + 1, nxt);
#pragma unroll
            for (int j = 0; j < 4; j++)
#pragma unroll
                for (int i = 0; i < 4; i++) {
                    mma16(accg[i][j], af[cur][i], b1f[cur][j]);
                    mma16(accu[i][j], af[cur][i], b3f[cur][j]);
                }
        }
    }

    __half* hb = g_hh + ((size_t)e * T_TOK + m0) * H_DIM + n0;
#pragma unroll
    for (int i = 0; i < 4; i++) {
        const int r0 = warp_m + i * 16 + gq;
        const int r1 = r0 + 8;
#pragma unroll
        for (int j = 0; j < 4; j++) {
            const int col = warp_n + j * 8 + tq * 2;
            if (m0 + r0 < cnt) {
                half2 o = __floats2half2_rn(silu_mul(accg[i][j][0], accu[i][j][0]),
                                            silu_mul(accg[i][j][1], accu[i][j][1]));
                *(half2*)(hb + (size_t)r0 * H_DIM + col) = o;
            }
            if (m0 + r1 < cnt) {
                half2 o = __floats2half2_rn(silu_mul(accg[i][j][2], accu[i][j][2]),
                                            silu_mul(accg[i][j][3], accu[i][j][3]));
                *(half2*)(hb + (size_t)r1 * H_DIM + col) = o;
            }
        }
    }
}

// ---------------- gemm2: down = w_m * (H @ w2). BM=128,BN=128,KC=64. warp 64x64.
__global__ __launch_bounds__(128, 2) void gemm2_mma(){
    const int e = blockIdx.z, cnt = g_cnt[e], m0 = blockIdx.y * 128;
    if (m0 >= cnt) return;
    const int n0 = blockIdx.x * 128;

    const uint32_t sbase = smem_u32(dyn);
    const int tid = threadIdx.x, wid = tid >> 5, lane = tid & 31;
    const int gq = lane >> 2, tq = lane & 3;
    const int warp_m = (wid & 1) * 64, warp_n = (wid >> 1) * 64;

    const __half* hs = g_hh + ((size_t)e * T_TOK + min(m0 + tid, cnt - 1)) * H_DIM;  // + kg
    const int brow = tid >> 1, bhw = (tid & 1) * 64;
    const __half* w2s = g_w2h + ((size_t)e * H_DIM + brow) * D_DIM + n0 + bhw;       // + kg*D
    const uint32_t dA = sbase + (uint32_t)tid * 144u;
    const uint32_t dB = sbase + B2OFFB + (uint32_t)(brow * 272 + bhw * 2);

    auto fill = [&](int c){
        const uint32_t bo = (uint32_t)(c % 3) * BUFB2;
        const int kg = c * KC;
        const __half* pa = hs + kg;
#pragma unroll
        for (int i = 0; i < 8; i++) cpa16(dA + bo + i * 16, pa + i * 8);
        const __half* pb = w2s + (size_t)kg * D_DIM;
#pragma unroll
        for (int i = 0; i < 8; i++) cpa16(dB + bo + i * 16, pb + i * 8);
    };

    uint32_t a_off[4];
#pragma unroll
    for (int i = 0; i < 4; i++)
        a_off[i] = (uint32_t)(((warp_m + i * 16 + (lane & 15)) * 72 + (lane >> 4) * 8) * 2);
    uint32_t b_off[4];
#pragma unroll
    for (int p = 0; p < 4; p++)
        b_off[p] = (uint32_t)(B2OFFB + ((lane & 15) * 136 + warp_n + p * 16 + (lane >> 4) * 8) * 2);

    float acc[4][8][4];
#pragma unroll
    for (int i = 0; i < 4; i++)
#pragma unroll
        for (int j = 0; j < 8; j++)
#pragma unroll
            for (int q = 0; q < 4; q++) acc[i][j][q] = 0.f;

    const int NC = H_DIM / KC;  // 44
    fill(0); CP_COMMIT();
    fill(1); CP_COMMIT();

    for (int c = 0; c < NC; c++) {
        CP_WAIT1();
        __syncthreads();
        if (c + 2 < NC) fill(c + 2);
        CP_COMMIT();

        const uint32_t abuf = sbase + (uint32_t)(c % 3) * BUFB2;
        uint32_t af[2][4][4], bf[2][8][2];

        auto ldfr = [&](int ks, int buf){
#pragma unroll
            for (int i = 0; i < 4; i++) ldsm4(af[buf][i], abuf + a_off[i] + ks * 32);
#pragma unroll
            for (int p = 0; p < 4; p++) {
                uint32_t d[4];
                ldsm4t(d, abuf + b_off[p] + ks * 4352);
                bf[buf][2*p][0] = d[0]; bf[buf][2*p][1] = d[1];
                bf[buf][2*p+1][0] = d[2]; bf[buf][2*p+1][1] = d[3];
            }
        };
        ldfr(0, 0);
#pragma unroll
        for (int ks = 0; ks < 4; ks++) {
            const int cur = ks & 1, nxt = cur ^ 1;
            if (ks < 3) ldfr(ks + 1, nxt);
#pragma unroll
            for (int j = 0; j < 8; j++)
#pragma unroll
                for (int i = 0; i < 4; i++) mma16(acc[i][j], af[cur][i], bf[cur][j]);
        }
    }

    float* db = g_down + ((size_t)e * T_TOK + m0) * D_DIM + n0;
#pragma unroll
    for (int i = 0; i < 4; i++) {
        const int r0 = warp_m + i * 16 + gq;
        const int r1 = r0 + 8;
        const float wg0 = g_slot_w[e * T_TOK + min(m0 + r0, cnt - 1)];
        const float wg1 = g_slot_w[e * T_TOK + min(m0 + r1, cnt - 1)];
#pragma unroll
        for (int j = 0; j < 8; j++) {
            const int col = warp_n + j * 8 + tq * 2;
            if (m0 + r0 < cnt) {
                float2 o; o.x = acc[i][j][0] * wg0; o.y = acc[i][j][1] * wg0;
                *(float2*)(db + (size_t)r0 * D_DIM + col) = o;
            }
            if (m0 + r1 < cnt) {
                float2 o; o.x = acc[i][j][2] * wg1; o.y = acc[i][j][3] * wg1;
                *(float2*)(db + (size_t)r1 * D_DIM + col) = o;
            }
        }
    }
}

// ---------------- launch ----------------
extern "C" void kernel_launch(void* const* d_in, const int* in_sizes, int n_in,
                              void* d_out, int out_size){
    const float* x  = (const float*)d_in[0];
    const float* wg = (const float*)d_in[1];
    const float* w1 = (const float*)d_in[2];
    const float* w2 = (const float*)d_in[3];
    const float* w3 = (const float*)d_in[4];
    float* out = (float*)d_out;

    const int smem13 = 3 * BUFB13;  // 110592
    const int smem2  = 3 * BUFB2;   // 107520
    cudaFuncSetAttribute(gemm13_mma, cudaFuncAttributeMaxDynamicSharedMemorySize, smem13);
    cudaFuncSetAttribute(gemm2_mma,  cudaFuncAttributeMaxDynamicSharedMemorySize, smem2);

    __half* xh;  cudaGetSymbolAddress((void**)&xh,  g_xh);
    __half* w1h; cudaGetSymbolAddress((void**)&w1h, g_w1h);
    __half* w3h; cudaGetSymbolAddress((void**)&w3h, g_w3h);
    __half* w2h; cudaGetSymbolAddress((void**)&w2h, g_w2h);

    const int nw8 = (E_NUM * D_DIM * H_DIM) / 8;   // 2883584
    const int nx8 = (T_TOK * D_DIM) / 8;           // 524288

    zero_cnt_kernel<<<1, 32>>>();
    gating_kernel<<<T_TOK, 256>>>(x, wg);
    cvt_f16_kernel<<<(nx8 + 255) / 256, 256>>>(x,  xh,  nx8);
    cvt_f16_kernel<<<(nw8 + 255) / 256, 256>>>(w1, w1h, nw8);
    cvt_f16_kernel<<<(nw8 + 255) / 256, 256>>>(w3, w3h, nw8);
    cvt_f16_kernel<<<(nw8 + 255) / 256, 256>>>(w2, w2h, nw8);
    gemm13_mma<<<dim3(H_DIM / 64, T_TOK / 128, E_NUM), 128, smem13>>>();
    gemm2_mma<<<dim3(D_DIM / 128, T_TOK / 128, E_NUM), 128, smem2>>>();
    combine_kernel<<<T_TOK, 256>>>(out);
}